// round 5
// baseline (speedup 1.0000x reference)
#include <cuda_runtime.h>
#include <cstdint>

#define NNODES 100000
#define NEDGES 1600000
#define KF     48

// ---------------------------------------------------------------------------
// Scratch (all __device__ globals; no allocations)
// ---------------------------------------------------------------------------
__device__ float g_scratch[2u * NNODES * KF];    // [x_pos | x_neg] sums
__device__ int   g_deg   [2 * NNODES];           // per-dst degree (per set)
__device__ int   g_base  [2 * (NNODES + 1)];     // exclusive scan (per set)
__device__ int   g_work  [2 * NNODES];           // running placement cursor
__device__ int   g_sorted[2 * NEDGES];           // src ids bucketed by dst
__device__ int   g_is64;                         // 1 if indices are int64

// ---- packed f32x2 helpers (Blackwell FFMA2 path; ptxas never auto-fuses) ----
#define PACK_F32X2(out, lo, hi) \
    asm("mov.b64 %0, {%1, %2};" : "=l"(out) : "f"(lo), "f"(hi))
#define UNPACK_F32X2(lo, hi, in) \
    asm("mov.b64 {%0, %1}, %2;" : "=f"(lo), "=f"(hi) : "l"(in))
#define FMA_F32X2(d, a, b) \
    asm("fma.rn.f32x2 %0, %1, %2, %3;" : "=l"(d) : "l"(a), "l"(b), "l"(d))

// ---------------------------------------------------------------------------
// K0: zero degree counters + dtype probe (block 0).
// For int64 indices in [0,1e5) every odd 32-bit word is 0; for int32 random
// indices, sampled odd words are ~never all zero.
// ---------------------------------------------------------------------------
__global__ void zero_probe_kernel(const unsigned int* __restrict__ p, int n_idx) {
    int i = blockIdx.x * blockDim.x + threadIdx.x;
    if (i < 2 * NNODES) g_deg[i] = 0;
    if (blockIdx.x == 0) {
        __shared__ int any_nonzero;
        if (threadIdx.x == 0) any_nonzero = 0;
        __syncthreads();
        int stride = n_idx / 4096;
        if (stride < 1) stride = 1;
        for (int s = threadIdx.x; s < 4096; s += blockDim.x) {
            long long w = (long long)s * stride;
            if (w >= n_idx) break;
            if (p[2 * w + 1] != 0u) any_nonzero = 1;   // benign race
        }
        __syncthreads();
        if (threadIdx.x == 0) g_is64 = any_nonzero ? 0 : 1;
    }
}

// ---------------------------------------------------------------------------
// K1: histogram of destination nodes, both edge sets in one grid.
// ---------------------------------------------------------------------------
__global__ void hist_kernel(const void* __restrict__ pos,
                            const void* __restrict__ neg, int E) {
    long long gid = (long long)blockIdx.x * blockDim.x + threadIdx.x;
    if (gid >= 2LL * E) return;
    int set = gid >= E;
    long long e = gid - (long long)set * E;
    const void* idx = set ? neg : pos;
    int dst = g_is64 ? (int)((const long long*)idx)[e + E]
                     : ((const int*)idx)[e + E];
    atomicAdd(&g_deg[set * NNODES + dst], 1);
}

// ---------------------------------------------------------------------------
// K2: exclusive scan of degrees -> g_base, g_work. One block per edge set.
// ---------------------------------------------------------------------------
__global__ void scan_kernel(int N) {
    __shared__ int ssum[1024];
    const int set = blockIdx.x;
    const int t = threadIdx.x;
    const int CH = (N + 1023) / 1024;
    int begin = t * CH;
    int end = begin + CH; if (end > N) end = N;

    int s = 0;
    for (int i = begin; i < end; i++) s += g_deg[set * NNODES + i];
    ssum[t] = s;
    __syncthreads();
    // Hillis-Steele inclusive scan over 1024 partial sums
    for (int off = 1; off < 1024; off <<= 1) {
        int v = (t >= off) ? ssum[t - off] : 0;
        __syncthreads();
        ssum[t] += v;
        __syncthreads();
    }
    int run = (t > 0) ? ssum[t - 1] : 0;
    for (int i = begin; i < end; i++) {
        g_base[set * (NNODES + 1) + i] = run;
        g_work[set * NNODES + i] = run;
        run += g_deg[set * NNODES + i];
    }
    if (t == 1023) g_base[set * (NNODES + 1) + N] = ssum[1023];
}

// ---------------------------------------------------------------------------
// K3: place src ids into dst-buckets (counting-sort scatter pass).
// ---------------------------------------------------------------------------
__global__ void place_kernel(const void* __restrict__ pos,
                             const void* __restrict__ neg, int E) {
    long long gid = (long long)blockIdx.x * blockDim.x + threadIdx.x;
    if (gid >= 2LL * E) return;
    int set = gid >= E;
    long long e = gid - (long long)set * E;
    const void* idx = set ? neg : pos;
    int src, dst;
    if (g_is64) {
        const long long* p = (const long long*)idx;
        src = (int)p[e];
        dst = (int)p[e + E];
    } else {
        const int* p = (const int*)idx;
        src = p[e];
        dst = p[e + E];
    }
    int slot = atomicAdd(&g_work[set * NNODES + dst], 1);
    g_sorted[set * NEDGES + slot] = src;
}

// ---------------------------------------------------------------------------
// K4: segmented gather-sum. 4 lanes per (set,node); lane q owns float4
// chunks q, q+4, q+8 of the 48-col row. Register accumulation, single store
// per chunk -> no float atomics, no pre-zeroing.
// ---------------------------------------------------------------------------
__global__ void gather_sum_kernel(const float* __restrict__ x, int N) {
    long long gid = (long long)blockIdx.x * blockDim.x + threadIdx.x;
    int q = (int)(gid & 3);
    long long m = gid >> 2;
    if (m >= 2LL * N) return;
    int set = m >= N;
    int n = (int)(m - (long long)set * N);

    int start = g_base[set * (NNODES + 1) + n];
    int end   = g_base[set * (NNODES + 1) + n + 1];
    const int* ss = &g_sorted[set * NEDGES];

    float4 a0 = make_float4(0.f, 0.f, 0.f, 0.f), a1 = a0, a2 = a0;
    for (int e = start; e < end; e++) {
        const float4* xr = (const float4*)(x + (size_t)ss[e] * KF);
        float4 v0 = xr[q], v1 = xr[q + 4], v2 = xr[q + 8];
        a0.x += v0.x; a0.y += v0.y; a0.z += v0.z; a0.w += v0.w;
        a1.x += v1.x; a1.y += v1.y; a1.z += v1.z; a1.w += v1.w;
        a2.x += v2.x; a2.y += v2.y; a2.z += v2.z; a2.w += v2.w;
    }
    float4* orow = (float4*)(g_scratch + ((size_t)set * NNODES + n) * KF);
    orow[q]     = a0;
    orow[q + 4] = a1;
    orow[q + 8] = a2;
}

// ---------------------------------------------------------------------------
// K5: per-node fused MLP + softmax, packed-f32x2 math (unchanged from R4).
// ---------------------------------------------------------------------------
__global__ void __launch_bounds__(128, 3)
node_kernel(const float* __restrict__ x,
            const float* __restrict__ W1,
            const float* __restrict__ b1,
            const float* __restrict__ W2,
            const float* __restrict__ b2,
            float* __restrict__ out,
            int N) {
    __shared__ float W1s[144 * 16];
    __shared__ float W2s[16 * 48];
    __shared__ float b1s[16];
    __shared__ float b2s[48];

    for (int i = threadIdx.x; i < 144 * 16; i += blockDim.x) W1s[i] = W1[i];
    for (int i = threadIdx.x; i < 16 * 48;  i += blockDim.x) W2s[i] = W2[i];
    if (threadIdx.x < 16) b1s[threadIdx.x] = b1[threadIdx.x];
    if (threadIdx.x < 48) b2s[threadIdx.x] = b2[threadIdx.x];
    __syncthreads();

    int n = blockIdx.x * blockDim.x + threadIdx.x;
    if (n >= N) return;

    unsigned long long hp[8];
#pragma unroll
    for (int j = 0; j < 8; j++) PACK_F32X2(hp[j], b1s[2 * j], b1s[2 * j + 1]);

    const float* src0 = x + (size_t)n * KF;
    const float* src1 = g_scratch + (size_t)n * KF;
    const float* src2 = g_scratch + (size_t)(NNODES + n) * KF;

    for (int s = 0; s < 3; s++) {
        const float4* sp4 = (const float4*)((s == 0) ? src0 : (s == 1) ? src1 : src2);
        for (int c = 0; c < 12; c++) {
            float4 v = sp4[c];
            const ulonglong2* w = (const ulonglong2*)&W1s[(s * 48 + c * 4) * 16];
            const float vv[4] = {v.x, v.y, v.z, v.w};
#pragma unroll
            for (int r = 0; r < 4; r++) {
                unsigned long long a;
                PACK_F32X2(a, vv[r], vv[r]);
#pragma unroll
                for (int u = 0; u < 4; u++) {
                    ulonglong2 wb = w[4 * r + u];
                    FMA_F32X2(hp[2 * u + 0], a, wb.x);
                    FMA_F32X2(hp[2 * u + 1], a, wb.y);
                }
            }
        }
    }

    float h[16];
#pragma unroll
    for (int j = 0; j < 8; j++) UNPACK_F32X2(h[2 * j], h[2 * j + 1], hp[j]);
#pragma unroll
    for (int j = 0; j < 16; j++) h[j] = tanhf(h[j]);

    unsigned long long Cp[24];
#pragma unroll
    for (int p = 0; p < 24; p++) PACK_F32X2(Cp[p], b2s[2 * p], b2s[2 * p + 1]);

#pragma unroll
    for (int j = 0; j < 16; j++) {
        unsigned long long a;
        PACK_F32X2(a, h[j], h[j]);
        const ulonglong2* w = (const ulonglong2*)&W2s[j * 48];
#pragma unroll
        for (int u = 0; u < 12; u++) {
            ulonglong2 wb = w[u];
            FMA_F32X2(Cp[2 * u + 0], a, wb.x);
            FMA_F32X2(Cp[2 * u + 1], a, wb.y);
        }
    }

    float C[48];
#pragma unroll
    for (int p = 0; p < 24; p++) UNPACK_F32X2(C[2 * p], C[2 * p + 1], Cp[p]);

    float m = C[0];
#pragma unroll
    for (int c = 1; c < 48; c++) m = fmaxf(m, C[c]);
    float sum = 0.f;
#pragma unroll
    for (int c = 0; c < 48; c++) { C[c] = __expf(C[c] - m); sum += C[c]; }
    float inv = 1.0f / sum;
#pragma unroll
    for (int c = 0; c < 48; c++) C[c] *= inv;

    float4* o4 = (float4*)(out + (size_t)n * KF);
#pragma unroll
    for (int c = 0; c < 12; c++)
        o4[c] = make_float4(C[4 * c], C[4 * c + 1], C[4 * c + 2], C[4 * c + 3]);
}

// ---------------------------------------------------------------------------
// Launch
// ---------------------------------------------------------------------------
extern "C" void kernel_launch(void* const* d_in, const int* in_sizes, int n_in,
                              void* d_out, int out_size) {
    const float* x   = (const float*)d_in[0];
    const void*  pos = d_in[1];
    const void*  neg = d_in[2];
    const float* W1  = (const float*)d_in[3];
    const float* b1  = (const float*)d_in[4];
    const float* W2  = (const float*)d_in[5];
    const float* b2  = (const float*)d_in[6];
    float* out = (float*)d_out;

    int N = in_sizes[0] / KF;          // 100000
    int E = in_sizes[1] / 2;           // 1600000
    if (N > NNODES) N = NNODES;
    if (E > NEDGES) E = NEDGES;

    // K0: zero counters + dtype probe
    zero_probe_kernel<<<(2 * NNODES + 255) / 256, 256>>>((const unsigned int*)pos, E);

    // K1: per-dst histogram (both sets)
    long long tE = 2LL * E;
    hist_kernel<<<(int)((tE + 255) / 256), 256>>>(pos, neg, E);

    // K2: exclusive scan -> base/work
    scan_kernel<<<2, 1024>>>(N);

    // K3: bucket edges by dst
    place_kernel<<<(int)((tE + 255) / 256), 256>>>(pos, neg, E);

    // K4: segmented gather-sum into scratch (4 lanes / node / set)
    long long tg = 2LL * N * 4;
    gather_sum_kernel<<<(int)((tg + 255) / 256), 256>>>(x, N);

    // K5: fused MLP + softmax per node
    node_kernel<<<(N + 127) / 128, 128>>>(x, W1, b1, W2, b2, out, N);
}

// round 10
// speedup vs baseline: 2.9427x; 2.9427x over previous
#include <cuda_runtime.h>
#include <cstdint>

#define NNODES 100000
#define KF     48

// ---------------------------------------------------------------------------
// Scratch (__device__ globals; no allocations)
// ---------------------------------------------------------------------------
// g_proj[n][0:16]=u=x@W1a+b1, [16:32]=v=x@W1b, [32:48]=w=x@W1c
__device__ float g_proj[(size_t)NNODES * KF];
// g_hsum[set][n][16]: scatter-add accumulators for v (pos) / w (neg)
__device__ float g_hsum[2u * NNODES * 16];
__device__ int   g_is64;   // 1 if edge indices are int64

// ---- packed f32x2 helpers (Blackwell FFMA2; ptxas never auto-fuses) ----
#define PACK_F32X2(out, lo, hi) \
    asm("mov.b64 %0, {%1, %2};" : "=l"(out) : "f"(lo), "f"(hi))
#define UNPACK_F32X2(lo, hi, in) \
    asm("mov.b64 {%0, %1}, %2;" : "=f"(lo), "=f"(hi) : "l"(in))
#define FMA_F32X2(d, a, b) \
    asm("fma.rn.f32x2 %0, %1, %2, %3;" : "=l"(d) : "l"(a), "l"(b), "l"(d))

// ---------------------------------------------------------------------------
// K0: dtype probe (1 block). For int64 indices in [0,1e5) every odd 32-bit
// word is 0; for random int32 indices sampled odd words are ~never all zero.
// ---------------------------------------------------------------------------
__global__ void probe_kernel(const unsigned int* __restrict__ p, int n_idx) {
    __shared__ int any_nonzero;
    if (threadIdx.x == 0) any_nonzero = 0;
    __syncthreads();
    int stride = n_idx / 4096;
    if (stride < 1) stride = 1;
    for (int s = threadIdx.x; s < 4096; s += blockDim.x) {
        long long w = (long long)s * stride;
        if (w >= n_idx) break;
        if (p[2 * w + 1] != 0u) any_nonzero = 1;   // benign race
    }
    __syncthreads();
    if (threadIdx.x == 0) g_is64 = any_nonzero ? 0 : 1;
}

// ---------------------------------------------------------------------------
// K1: projection. Per node: [u|v|w] = x_n @ [W1a|W1b|W1c], u += b1.
// Weights staged in shared (warp-uniform LDS.128 broadcast), packed FFMA2.
// ---------------------------------------------------------------------------
__global__ void __launch_bounds__(128, 3)
project_kernel(const float* __restrict__ x,
               const float* __restrict__ W1,
               const float* __restrict__ b1,
               int N) {
    __shared__ float W1s[144 * 16];
    __shared__ float b1s[16];
    for (int i = threadIdx.x; i < 144 * 16; i += blockDim.x) W1s[i] = W1[i];
    if (threadIdx.x < 16) b1s[threadIdx.x] = b1[threadIdx.x];
    __syncthreads();

    int n = blockIdx.x * blockDim.x + threadIdx.x;
    if (n >= N) return;

    // hp[b][u]: block b (u/v/w), 8 packed f32x2 accumulators each
    unsigned long long hp[3][8];
#pragma unroll
    for (int j = 0; j < 8; j++) {
        PACK_F32X2(hp[0][j], b1s[2 * j], b1s[2 * j + 1]);
        unsigned long long z;
        PACK_F32X2(z, 0.f, 0.f);
        hp[1][j] = z;
        hp[2][j] = z;
    }

    const float4* xp4 = (const float4*)(x + (size_t)n * KF);
    for (int c = 0; c < 12; c++) {
        float4 v4 = xp4[c];
        const float vv[4] = {v4.x, v4.y, v4.z, v4.w};
#pragma unroll
        for (int r = 0; r < 4; r++) {
            int i = 4 * c + r;               // input element 0..47
            unsigned long long a;
            PACK_F32X2(a, vv[r], vv[r]);
#pragma unroll
            for (int b = 0; b < 3; b++) {
                const ulonglong2* w = (const ulonglong2*)&W1s[(b * 48 + i) * 16];
#pragma unroll
                for (int u = 0; u < 4; u++) {
                    ulonglong2 wb = w[u];
                    FMA_F32X2(hp[b][2 * u + 0], a, wb.x);
                    FMA_F32X2(hp[b][2 * u + 1], a, wb.y);
                }
            }
        }
    }

    float4* o4 = (float4*)(g_proj + (size_t)n * KF);
#pragma unroll
    for (int b = 0; b < 3; b++) {
#pragma unroll
        for (int u = 0; u < 4; u++) {
            float lo0, hi0, lo1, hi1;
            UNPACK_F32X2(lo0, hi0, hp[b][2 * u + 0]);
            UNPACK_F32X2(lo1, hi1, hp[b][2 * u + 1]);
            o4[b * 4 + u] = make_float4(lo0, hi0, lo1, hi1);
        }
    }
}

// ---------------------------------------------------------------------------
// K2: edge scatter-add of 16-wide projected rows. 4 lanes per edge, one
// float4 each. Global edge id in [0, 2E): [0,E)->pos (uses v), [E,2E)->neg
// (uses w). red.global.add.v4.f32.
// ---------------------------------------------------------------------------
__global__ void scatter_kernel(const void* __restrict__ pos_idx,
                               const void* __restrict__ neg_idx,
                               int E, int N) {
    long long gid = (long long)blockIdx.x * blockDim.x + threadIdx.x;
    int q = (int)(gid & 3);
    long long eg = gid >> 2;
    if (eg >= 2LL * E) return;

    int set;
    const void* idx;
    long long e;
    if (eg < E) { set = 0; idx = pos_idx; e = eg; }
    else        { set = 1; idx = neg_idx; e = eg - E; }

    int src, dst;
    if (g_is64) {
        const long long* p = (const long long*)idx;
        src = (int)p[e];
        dst = (int)p[e + E];
    } else {
        const int* p = (const int*)idx;
        src = p[e];
        dst = p[e + E];
    }

    // v at row offset 16 floats, w at 32
    const float4* vr = (const float4*)(g_proj + (size_t)src * KF + (1 + set) * 16);
    float4 v = vr[q];
    float* addr = g_hsum + ((size_t)set * N + dst) * 16 + 4 * q;
    asm volatile(
        "red.global.add.v4.f32 [%0], {%1, %2, %3, %4};"
        :: "l"(addr), "f"(v.x), "f"(v.y), "f"(v.z), "f"(v.w)
        : "memory");
}

// ---------------------------------------------------------------------------
// K3: per-node epilogue. h = tanh(u + spos + sneg); C = h@W2 + b2; softmax.
// ---------------------------------------------------------------------------
__global__ void __launch_bounds__(128, 3)
node_kernel(const float* __restrict__ W2,
            const float* __restrict__ b2,
            float* __restrict__ out,
            int N) {
    __shared__ float W2s[16 * 48];
    __shared__ float b2s[48];
    for (int i = threadIdx.x; i < 16 * 48; i += blockDim.x) W2s[i] = W2[i];
    if (threadIdx.x < 48) b2s[threadIdx.x] = b2[threadIdx.x];
    __syncthreads();

    int n = blockIdx.x * blockDim.x + threadIdx.x;
    if (n >= N) return;

    const float4* up = (const float4*)(g_proj + (size_t)n * KF);        // u (has b1)
    const float4* sp = (const float4*)(g_hsum + (size_t)n * 16);        // pos sums
    const float4* sn = (const float4*)(g_hsum + ((size_t)N + n) * 16);  // neg sums

    float h[16];
#pragma unroll
    for (int u = 0; u < 4; u++) {
        float4 a = up[u], b = sp[u], c = sn[u];
        h[4 * u + 0] = tanhf(a.x + b.x + c.x);
        h[4 * u + 1] = tanhf(a.y + b.y + c.y);
        h[4 * u + 2] = tanhf(a.z + b.z + c.z);
        h[4 * u + 3] = tanhf(a.w + b.w + c.w);
    }

    // C = h @ W2 + b2 (24 packed pairs)
    unsigned long long Cp[24];
#pragma unroll
    for (int p = 0; p < 24; p++) PACK_F32X2(Cp[p], b2s[2 * p], b2s[2 * p + 1]);
#pragma unroll
    for (int j = 0; j < 16; j++) {
        unsigned long long a;
        PACK_F32X2(a, h[j], h[j]);
        const ulonglong2* w = (const ulonglong2*)&W2s[j * 48];  // 12 ull2
#pragma unroll
        for (int u = 0; u < 12; u++) {
            ulonglong2 wb = w[u];
            FMA_F32X2(Cp[2 * u + 0], a, wb.x);
            FMA_F32X2(Cp[2 * u + 1], a, wb.y);
        }
    }

    float C[48];
#pragma unroll
    for (int p = 0; p < 24; p++) UNPACK_F32X2(C[2 * p], C[2 * p + 1], Cp[p]);

    float m = C[0];
#pragma unroll
    for (int c = 1; c < 48; c++) m = fmaxf(m, C[c]);
    float sum = 0.f;
#pragma unroll
    for (int c = 0; c < 48; c++) { C[c] = __expf(C[c] - m); sum += C[c]; }
    float inv = 1.0f / sum;
#pragma unroll
    for (int c = 0; c < 48; c++) C[c] *= inv;

    float4* o4 = (float4*)(out + (size_t)n * KF);
#pragma unroll
    for (int c = 0; c < 12; c++)
        o4[c] = make_float4(C[4 * c], C[4 * c + 1], C[4 * c + 2], C[4 * c + 3]);
}

// ---------------------------------------------------------------------------
// Launch
// inputs: 0:x [N,48] f32, 1:pos_edge_index [2,E], 2:neg_edge_index [2,E],
//         3:W1 [144,16] f32, 4:b1 [16] f32, 5:W2 [16,48] f32, 6:b2 [48] f32
// ---------------------------------------------------------------------------
extern "C" void kernel_launch(void* const* d_in, const int* in_sizes, int n_in,
                              void* d_out, int out_size) {
    const float* x   = (const float*)d_in[0];
    const void*  pos = d_in[1];
    const void*  neg = d_in[2];
    const float* W1  = (const float*)d_in[3];
    const float* b1  = (const float*)d_in[4];
    const float* W2  = (const float*)d_in[5];
    const float* b2  = (const float*)d_in[6];
    float* out = (float*)d_out;

    int N = in_sizes[0] / KF;          // 100000
    int E = in_sizes[1] / 2;           // 1600000

    // K0: probe index dtype (tiny)
    probe_kernel<<<1, 256>>>((const unsigned int*)pos, E);

    // zero the 16-wide accumulators (graph-capturable memset node)
    void* hsum_ptr = nullptr;
    cudaGetSymbolAddress(&hsum_ptr, g_hsum);
    cudaMemsetAsync(hsum_ptr, 0, 2ull * N * 16 * sizeof(float));

    // K1: project x -> [u|v|w] (16 each)
    project_kernel<<<(N + 127) / 128, 128>>>(x, W1, b1, N);

    // K2: scatter-add projected 16-wide rows (4 lanes / edge)
    long long total = 2LL * E * 4;
    scatter_kernel<<<(int)((total + 255) / 256), 256>>>(pos, neg, E, N);

    // K3: epilogue per node
    node_kernel<<<(N + 127) / 128, 128>>>(W2, b2, out, N);
}